// round 3
// baseline (speedup 1.0000x reference)
#include <cuda_runtime.h>
#include <math.h>

#define NB 8
#define NC 64
#define NH 224
#define NW 224
#define HW (NH*NW)

// Scratch (device globals; no allocation allowed)
__device__ float g_lrb[2*NB*64*64];   // [orient][b][d][e]
__device__ float g_srb[2*NB*512];     // [orient][b][head][d][e]
__device__ float g_rowsum[NB*NC*NH];  // sum over w
__device__ float g_colsum[NB*NC*NW];  // sum over h
__device__ float g_gate[NB*NC];       // sigmoid(attn) per (b,c)

// ---------------------------------------------------------------------------
__global__ void zero_kernel() {
    int i = blockIdx.x*256 + threadIdx.x;
    if (i < 2*NB*64*64) g_lrb[i] = 0.f;
    if (i < 2*NB*512)   g_srb[i] = 0.f;
}

// ---------------------------------------------------------------------------
// Row sums (over w) and column sums (over h) of x — feeds v_mean computation.
__global__ void sums_kernel(const float* __restrict__ x) {
    int bc = blockIdx.x;                       // 0..511 = b*64+c
    const float* p = x + (size_t)bc * HW;
    __shared__ float part[NH][8];
    int t = threadIdx.x, lane = t & 31, wid = t >> 5;
    float colacc = 0.f;
    for (int r = 0; r < NH; ++r) {
        float v = (t < NW) ? p[r*NW + t] : 0.f;
        colacc += v;
        #pragma unroll
        for (int o = 16; o; o >>= 1) v += __shfl_down_sync(0xffffffffu, v, o);
        if (lane == 0) part[r][wid] = v;
    }
    __syncthreads();
    if (t < NH) {
        float rs = 0.f;
        #pragma unroll
        for (int k = 0; k < 8; ++k) rs += part[t][k];
        g_rowsum[bc*NH + t] = rs;
    }
    if (t < NW) g_colsum[bc*NW + t] = colacc;
}

// ---------------------------------------------------------------------------
// Fused depthwise conv (q:7 taps, k:11 taps, both branches) + Gram accumulate.
// grid = (28, 8, 2): 28 tiles of 8 positions, batch, orientation (0=h, 1=w).
// Streams 224 steps along the conv axis with an 11-deep register window.
__global__ void __launch_bounds__(256,2) gram_kernel(
    const float* __restrict__ x,
    const float* __restrict__ lqh, const float* __restrict__ lkh,
    const float* __restrict__ sqh, const float* __restrict__ skh,
    const float* __restrict__ lqw, const float* __restrict__ lkw,
    const float* __restrict__ sqw, const float* __restrict__ skw)
{
    const int orient = blockIdx.z;
    const int b      = blockIdx.y;
    const int tile0  = blockIdx.x * 8;     // w0 (orient 0) or h0 (orient 1)
    const int t      = threadIdx.x;

    __shared__ __align__(16) float tl[NC*73];         // x tile [c][s][p], pad stride 73/9
    __shared__ __align__(16) float qk[2][4][8][64];   // [buf][qL,kL,qS,kS][pos][c]

    // conv role: channel cc, positions p0 and p0+4
    const int cc = t & 63;
    const int p0 = t >> 6;

    float wQL[7], wKL[11], wQS[7], wKS[11];
    {
        const float* a  = orient ? lqw : lqh;
        const float* bb = orient ? lkw : lkh;
        const float* c2 = orient ? sqw : sqh;
        const float* d2 = orient ? skw : skh;
        #pragma unroll
        for (int i = 0; i < 7;  ++i) wQL[i] = a [cc*7 +i];
        #pragma unroll
        for (int i = 0; i < 11; ++i) wKL[i] = bb[cc*11+i];
        #pragma unroll
        for (int i = 0; i < 7;  ++i) wQS[i] = c2[cc*7 +i];
        #pragma unroll
        for (int i = 0; i < 11; ++i) wKS[i] = d2[cc*11+i];
    }

    // gram role: lrb 4x4 tile (16x16 grid of tiles), srb 2 entries
    const int trow = t >> 4, tcol = t & 15;
    const int hq = t >> 5, dd = (t >> 2) & 7, e0 = (t & 3) << 1;

    float aL[4][4];
    #pragma unroll
    for (int i = 0; i < 4; ++i)
        #pragma unroll
        for (int j = 0; j < 4; ++j) aL[i][j] = 0.f;
    float aS0 = 0.f, aS1 = 0.f;

    float win0[11], win1[11];
    #pragma unroll
    for (int i = 0; i < 11; ++i) { win0[i] = 0.f; win1[i] = 0.f; }

    const float* xb = x + (size_t)b * NC * HW;

    for (int ckk = 0; ckk < 29; ++ckk) {
        __syncthreads();  // all reads of previous tile chunk done
        // stage 8 stream-steps x 8 positions x 64 channels
        #pragma unroll
        for (int it = 0; it < 2; ++it) {
            int item = t + it*256;
            int c = item >> 3, u = item & 7;
            if (orient == 0) {
                int h = ckk*8 + u;                     // stream = h
                if (h < NH) {
                    const float4* src = (const float4*)(xb + (size_t)c*HW + h*NW + tile0);
                    float4 v0 = src[0], v1 = src[1];
                    float* d = &tl[c*73 + u*9];        // [c][s=u][p=v]
                    d[0]=v0.x; d[1]=v0.y; d[2]=v0.z; d[3]=v0.w;
                    d[4]=v1.x; d[5]=v1.y; d[6]=v1.z; d[7]=v1.w;
                }
            } else {
                int wc = ckk*8;                        // stream = w
                if (wc < NW) {
                    const float4* src = (const float4*)(xb + (size_t)c*HW + (tile0+u)*NW + wc);
                    float4 v0 = src[0], v1 = src[1];
                    float* d = &tl[c*73 + u];          // [c][s=v][p=u] (transposed store)
                    d[0] =v0.x; d[9] =v0.y; d[18]=v0.z; d[27]=v0.w;
                    d[36]=v1.x; d[45]=v1.y; d[54]=v1.z; d[63]=v1.w;
                }
            }
        }
        for (int j = 0; j < 8; ++j) {
            int sn = ckk*8 + j;                        // stream step
            if (sn > 229) break;                       // uniform across block
            __syncthreads();
            if (sn >= 6) {                             // consume step sn-1's q,k (row o=sn-6)
                int buf = sn & 1;
                #pragma unroll
                for (int p = 0; p < 8; ++p) {
                    float4 q4 = *(const float4*)&qk[buf][0][p][trow*4];
                    float4 k4 = *(const float4*)&qk[buf][1][p][tcol*4];
                    aL[0][0] += q4.x*k4.x; aL[0][1] += q4.x*k4.y; aL[0][2] += q4.x*k4.z; aL[0][3] += q4.x*k4.w;
                    aL[1][0] += q4.y*k4.x; aL[1][1] += q4.y*k4.y; aL[1][2] += q4.y*k4.z; aL[1][3] += q4.y*k4.w;
                    aL[2][0] += q4.z*k4.x; aL[2][1] += q4.z*k4.y; aL[2][2] += q4.z*k4.z; aL[2][3] += q4.z*k4.w;
                    aL[3][0] += q4.w*k4.x; aL[3][1] += q4.w*k4.y; aL[3][2] += q4.w*k4.z; aL[3][3] += q4.w*k4.w;
                    float  qs = qk[buf][2][p][hq*8+dd];
                    float2 ks = *(const float2*)&qk[buf][3][p][hq*8+e0];
                    aS0 += qs*ks.x; aS1 += qs*ks.y;
                }
            }
            if (sn <= 228) {
                float nv0 = 0.f, nv1 = 0.f;
                if (sn < 224) {                        // zero padding beyond edge
                    nv0 = tl[cc*73 + j*9 + p0];
                    nv1 = tl[cc*73 + j*9 + p0 + 4];
                }
                #pragma unroll
                for (int i2 = 0; i2 < 10; ++i2) { win0[i2] = win0[i2+1]; win1[i2] = win1[i2+1]; }
                win0[10] = nv0; win1[10] = nv1;
                if (sn >= 5) {                         // output row o = sn-5
                    int buf = (sn + 1) & 1;
                    float qL0=0.f,qL1=0.f,qS0v=0.f,qS1v=0.f;
                    #pragma unroll
                    for (int i2 = 0; i2 < 7; ++i2) {
                        qL0  += wQL[i2]*win0[2+i2]; qL1  += wQL[i2]*win1[2+i2];
                        qS0v += wQS[i2]*win0[2+i2]; qS1v += wQS[i2]*win1[2+i2];
                    }
                    float kL0=0.f,kL1=0.f,kS0v=0.f,kS1v=0.f;
                    #pragma unroll
                    for (int i2 = 0; i2 < 11; ++i2) {
                        kL0  += wKL[i2]*win0[i2]; kL1  += wKL[i2]*win1[i2];
                        kS0v += wKS[i2]*win0[i2]; kS1v += wKS[i2]*win1[i2];
                    }
                    qk[buf][0][p0][cc] = qL0;  qk[buf][0][p0+4][cc] = qL1;
                    qk[buf][1][p0][cc] = kL0;  qk[buf][1][p0+4][cc] = kL1;
                    qk[buf][2][p0][cc] = qS0v; qk[buf][2][p0+4][cc] = qS1v;
                    qk[buf][3][p0][cc] = kS0v; qk[buf][3][p0+4][cc] = kS1v;
                }
            }
        }
    }
    // accumulate partial Grams
    float* gl = &g_lrb[((orient*NB)+b)*4096];
    #pragma unroll
    for (int i = 0; i < 4; ++i)
        #pragma unroll
        for (int jj = 0; jj < 4; ++jj)
            atomicAdd(&gl[(trow*4+i)*64 + tcol*4 + jj], aL[i][jj]);
    float* gs = &g_srb[((orient*NB)+b)*512];
    atomicAdd(&gs[hq*64 + dd*8 + e0    ], aS0);
    atomicAdd(&gs[hq*64 + dd*8 + e0 + 1], aS1);
}

// ---------------------------------------------------------------------------
// v_mean from row/col sums + v weights, softmax(G), dot, mix, sigmoid.
// v-conv total sum = sum_a sums[a]*coeff(a), coeff(a)=sum_{i in [a-213,a+10]∩[0,20]} w[i].
// For a in [10,213] (204 positions) coeff is the full weight sum; edges handled
// with unrolled partial sums (no dynamically-indexed local arrays).
__global__ void finalize_kernel(
    const float* __restrict__ lvh, const float* __restrict__ lvw,
    const float* __restrict__ svh, const float* __restrict__ svw,
    const float* __restrict__ mixw)
{
    int b = blockIdx.x, t = threadIdx.x;
    __shared__ float vm[4][64];   // 0: h-lrb, 1: h-srb, 2: w-lrb, 3: w-srb
    __shared__ float res[4][64];
    if (t < 128) {
        int c = t & 63, which = t >> 6;   // 0 = h (rowsum), 1 = w (colsum)
        const float* sums = which ? &g_colsum[(b*64+c)*NW] : &g_rowsum[(b*64+c)*NH];
        const float* wL = (which ? lvw : lvh) + c*21;
        const float* wS = (which ? svw : svh) + c*21;
        float wLr[21], wSr[21];
        #pragma unroll
        for (int i = 0; i < 21; ++i) { wLr[i] = wL[i]; wSr[i] = wS[i]; }
        float wLtot = 0.f, wStot = 0.f;
        #pragma unroll
        for (int i = 0; i < 21; ++i) { wLtot += wLr[i]; wStot += wSr[i]; }
        // interior positions a=10..213: coeff = total weight sum
        float mid = 0.f;
        for (int a2 = 10; a2 <= 213; ++a2) mid += sums[a2];
        float accL = mid * wLtot, accS = mid * wStot;
        // left edge a=0..9: coeff = sum_{i=0..a+10} w[i]
        // right edge a=214..223: coeff = sum_{i=a-213..20} w[i]
        float pL = 0.f, pS = 0.f;
        #pragma unroll
        for (int i2 = 0; i2 <= 10; ++i2) { pL += wLr[i2]; pS += wSr[i2]; }  // prefix through i=10
        {
            float cpL = pL, cpS = pS;   // coeff for a=0
            #pragma unroll
            for (int a2 = 0; a2 < 10; ++a2) {
                float s = sums[a2];
                accL += s * cpL; accS += s * cpS;
                cpL += wLr[11 + a2]; cpS += wSr[11 + a2];  // extend prefix for a+1
            }
        }
        {
            float cpL = wLtot - wLr[0], cpS = wStot - wSr[0];  // coeff for a=214 (i from 1..20)
            #pragma unroll
            for (int a2 = 0; a2 < 10; ++a2) {
                float s = sums[214 + a2];
                accL += s * cpL; accS += s * cpS;
                cpL -= wLr[1 + a2]; cpS -= wSr[1 + a2];        // drop leading tap for a+1
            }
        }
        vm[which*2 + 0][c] = accL * (1.f/50176.f);
        vm[which*2 + 1][c] = accS * (1.f/50176.f);
    }
    __syncthreads();
    {
        int c = t & 63, role = t >> 6;     // 0 lrb-h, 1 lrb-w, 2 srb-h, 3 srb-w
        float r;
        if (role < 2) {
            const float* row = &g_lrb[((role*NB)+b)*4096 + c*64];
            const float* vmp = vm[role*2];
            float m = -1e30f;
            for (int e = 0; e < 64; ++e) { float v = row[e]*0.125f; if (v > m) m = v; }
            float se = 0.f, sd = 0.f;
            for (int e = 0; e < 64; ++e) {
                float ex = expf(row[e]*0.125f - m);
                se += ex; sd += ex*vmp[e];
            }
            r = sd/se;
        } else {
            int hh = c >> 3, ddd = c & 7;
            const float* row = &g_srb[(((role-2)*NB)+b)*512 + hh*64 + ddd*8];
            const float* vmp = vm[(role-2)*2 + 1] + hh*8;
            const float sc = 0.35355339059327373f;  // 8^-0.5
            float m = -1e30f;
            #pragma unroll
            for (int e = 0; e < 8; ++e) { float v = row[e]*sc; if (v > m) m = v; }
            float se = 0.f, sd = 0.f;
            #pragma unroll
            for (int e = 0; e < 8; ++e) {
                float ex = expf(row[e]*sc - m);
                se += ex; sd += ex*vmp[e];
            }
            r = sd/se;
        }
        res[role][c] = r;
    }
    __syncthreads();
    if (t < 64) {
        float a2 = mixw[0]*res[0][t] + mixw[1]*res[1][t]
                 + mixw[2]*res[2][t] + mixw[3]*res[3][t];
        g_gate[b*64 + t] = 1.f/(1.f + expf(-a2));
    }
}

// ---------------------------------------------------------------------------
__global__ void apply_kernel(const float* __restrict__ x, float* __restrict__ out) {
    int i = blockIdx.x*256 + threadIdx.x;      // over float4s
    if (i >= NB*NC*HW/4) return;
    float4 v = ((const float4*)x)[i];
    int bc = i / (HW/4);                       // HW/4 = 12544
    float s = g_gate[bc];
    v.x *= s; v.y *= s; v.z *= s; v.w *= s;
    ((float4*)out)[i] = v;
}

// ---------------------------------------------------------------------------
extern "C" void kernel_launch(void* const* d_in, const int* in_sizes, int n_in,
                              void* d_out, int out_size) {
    const float* x    = (const float*)d_in[0];
    const float* lqh  = (const float*)d_in[1];
    const float* lqw  = (const float*)d_in[2];
    const float* lkh  = (const float*)d_in[3];
    const float* lkw  = (const float*)d_in[4];
    const float* lvh  = (const float*)d_in[5];
    const float* lvw  = (const float*)d_in[6];
    const float* sqh  = (const float*)d_in[7];
    const float* sqw  = (const float*)d_in[8];
    const float* skh  = (const float*)d_in[9];
    const float* skw  = (const float*)d_in[10];
    const float* svh  = (const float*)d_in[11];
    const float* svw  = (const float*)d_in[12];
    const float* mixw = (const float*)d_in[13];
    float* out = (float*)d_out;

    zero_kernel<<<(2*NB*64*64 + 255)/256, 256>>>();
    sums_kernel<<<NB*NC, 256>>>(x);
    dim3 g(28, NB, 2);
    gram_kernel<<<g, 256>>>(x, lqh, lkh, sqh, skh, lqw, lkw, sqw, skw);
    finalize_kernel<<<NB, 256>>>(lvh, lvw, svh, svw, mixw);
    apply_kernel<<<(NB*NC*HW/4 + 255)/256, 256>>>(x, out);
}

// round 5
// speedup vs baseline: 1.2573x; 1.2573x over previous
#include <cuda_runtime.h>
#include <math.h>

#define NB 8
#define NC 64
#define NH 224
#define NW 224
#define HW (NH*NW)

// Scratch (device globals; no allocation allowed)
__device__ float g_lrb[2*NB*64*64];   // [orient][b][d][e]
__device__ float g_srb[2*NB*512];     // [orient][b][head][d][e]
__device__ float g_rowsum[NB*NC*NH];  // sum over w
__device__ float g_colsum[NB*NC*NW];  // sum over h
__device__ float g_vm[NB][4][64];     // v-means: [b][h-lrb,h-srb,w-lrb,w-srb][c]
__device__ float g_gate[NB*NC];       // sigmoid(attn) per (b,c)

// ---------------------------------------------------------------------------
__global__ void zero_kernel() {
    int i = blockIdx.x*256 + threadIdx.x;          // grid covers 114688
    if (i < 2*NB*64*64) g_lrb[i] = 0.f;
    if (i < 2*NB*512)   g_srb[i] = 0.f;
    if (i < NB*NC*NH) { g_rowsum[i] = 0.f; g_colsum[i] = 0.f; }
}

// ---------------------------------------------------------------------------
// Fused depthwise conv (q:7 taps, k:11 taps, both branches) + Gram accumulate
// + row/col sum accumulation.
// grid = (28, 8, 4): 28 tiles of 8 positions, batch, orient*2+half.
// Each block computes outputs o in [half*112, half*112+112) along the stream
// axis, streaming inputs with an 11-deep register window (10-step warm-up
// overlap for half 1).
__global__ void __launch_bounds__(256,2) gram_kernel(
    const float* __restrict__ x,
    const float* __restrict__ lqh, const float* __restrict__ lkh,
    const float* __restrict__ sqh, const float* __restrict__ skh,
    const float* __restrict__ lqw, const float* __restrict__ lkw,
    const float* __restrict__ sqw, const float* __restrict__ skw)
{
    const int orient = blockIdx.z >> 1;
    const int half   = blockIdx.z & 1;
    const int b      = blockIdx.y;
    const int tile0  = blockIdx.x * 8;     // w0 (orient 0) or h0 (orient 1)
    const int t      = threadIdx.x;

    const int o_lo = half * 112;
    const int o_hi = o_lo + 112;
    const int ck0  = half * 13;            // first staged chunk (13*8=104 >= 112-10)

    __shared__ __align__(16) float tl[NC*73];         // x tile [c][s][p], pad stride 73/9
    __shared__ __align__(16) float qk[2][4][8][64];   // [buf][qL,kL,qS,kS][pos][c]

    // conv role: channel cc, positions p0 and p0+4
    const int cc = t & 63;
    const int p0 = t >> 6;

    float wQL[7], wKL[11], wQS[7], wKS[11];
    {
        const float* a  = orient ? lqw : lqh;
        const float* bb = orient ? lkw : lkh;
        const float* c2 = orient ? sqw : sqh;
        const float* d2 = orient ? skw : skh;
        #pragma unroll
        for (int i = 0; i < 7;  ++i) wQL[i] = a [cc*7 +i];
        #pragma unroll
        for (int i = 0; i < 11; ++i) wKL[i] = bb[cc*11+i];
        #pragma unroll
        for (int i = 0; i < 7;  ++i) wQS[i] = c2[cc*7 +i];
        #pragma unroll
        for (int i = 0; i < 11; ++i) wKS[i] = d2[cc*11+i];
    }

    // gram role: lrb 4x4 tile (16x16 grid of tiles), srb 2 entries
    const int trow = t >> 4, tcol = t & 15;
    const int hq = t >> 5, dd = (t >> 2) & 7, e0 = (t & 3) << 1;

    float aL[4][4];
    #pragma unroll
    for (int i = 0; i < 4; ++i)
        #pragma unroll
        for (int j = 0; j < 4; ++j) aL[i][j] = 0.f;
    float aS0 = 0.f, aS1 = 0.f;
    float cs0 = 0.f, cs1 = 0.f;            // row/col sum partials for (cc, tile0+p0(+4))

    float win0[11], win1[11];
    #pragma unroll
    for (int i = 0; i < 11; ++i) { win0[i] = 0.f; win1[i] = 0.f; }

    const float* xb = x + (size_t)b * NC * HW;

    // one stream step (given chunk-local j and absolute sn); inlined by unroll
    #define STEP(J, SN)                                                              \
    {                                                                                \
        const int sn = (SN);                                                         \
        __syncthreads();                                                             \
        if (sn >= o_lo + 6 && sn < o_hi + 6) {       /* consume q,k of step sn-1 */  \
            int buf = sn & 1;                                                        \
            _Pragma("unroll")                                                        \
            for (int p = 0; p < 8; ++p) {                                            \
                float4 q4 = *(const float4*)&qk[buf][0][p][trow*4];                  \
                float4 k4 = *(const float4*)&qk[buf][1][p][tcol*4];                  \
                aL[0][0] += q4.x*k4.x; aL[0][1] += q4.x*k4.y; aL[0][2] += q4.x*k4.z; aL[0][3] += q4.x*k4.w; \
                aL[1][0] += q4.y*k4.x; aL[1][1] += q4.y*k4.y; aL[1][2] += q4.y*k4.z; aL[1][3] += q4.y*k4.w; \
                aL[2][0] += q4.z*k4.x; aL[2][1] += q4.z*k4.y; aL[2][2] += q4.z*k4.z; aL[2][3] += q4.z*k4.w; \
                aL[3][0] += q4.w*k4.x; aL[3][1] += q4.w*k4.y; aL[3][2] += q4.w*k4.z; aL[3][3] += q4.w*k4.w; \
                float  qs = qk[buf][2][p][hq*8+dd];                                  \
                float2 ks = *(const float2*)&qk[buf][3][p][hq*8+e0];                 \
                aS0 += qs*ks.x; aS1 += qs*ks.y;                                      \
            }                                                                        \
        }                                                                            \
        {                                                                            \
            float nv0 = 0.f, nv1 = 0.f;                                              \
            if (sn < 224) {                          /* zero padding beyond edge */  \
                nv0 = tl[cc*73 + (J)*9 + p0];                                        \
                nv1 = tl[cc*73 + (J)*9 + p0 + 4];                                    \
            }                                                                        \
            if (sn >= o_lo && sn < o_hi) { cs0 += nv0; cs1 += nv1; }                 \
            _Pragma("unroll")                                                        \
            for (int i2 = 0; i2 < 10; ++i2) { win0[i2] = win0[i2+1]; win1[i2] = win1[i2+1]; } \
            win0[10] = nv0; win1[10] = nv1;                                          \
            if (sn >= o_lo + 5 && sn < o_hi + 5) {   /* output row o = sn-5 */       \
                int buf = (sn + 1) & 1;                                              \
                float qL0=0.f,qL1=0.f,qS0v=0.f,qS1v=0.f;                             \
                _Pragma("unroll")                                                    \
                for (int i2 = 0; i2 < 7; ++i2) {                                     \
                    qL0  += wQL[i2]*win0[2+i2]; qL1  += wQL[i2]*win1[2+i2];          \
                    qS0v += wQS[i2]*win0[2+i2]; qS1v += wQS[i2]*win1[2+i2];          \
                }                                                                    \
                float kL0=0.f,kL1=0.f,kS0v=0.f,kS1v=0.f;                             \
                _Pragma("unroll")                                                    \
                for (int i2 = 0; i2 < 11; ++i2) {                                    \
                    kL0  += wKL[i2]*win0[i2]; kL1  += wKL[i2]*win1[i2];              \
                    kS0v += wKS[i2]*win0[i2]; kS1v += wKS[i2]*win1[i2];              \
                }                                                                    \
                qk[buf][0][p0][cc] = qL0;  qk[buf][0][p0+4][cc] = qL1;               \
                qk[buf][1][p0][cc] = kL0;  qk[buf][1][p0+4][cc] = kL1;               \
                qk[buf][2][p0][cc] = qS0v; qk[buf][2][p0+4][cc] = qS1v;              \
                qk[buf][3][p0][cc] = kS0v; qk[buf][3][p0+4][cc] = kS1v;              \
            }                                                                        \
        }                                                                            \
    }

    #define STAGE(CKK)                                                               \
    {                                                                                \
        __syncthreads();                                                             \
        _Pragma("unroll")                                                            \
        for (int it = 0; it < 2; ++it) {                                             \
            int item = t + it*256;                                                   \
            int c = item >> 3, u = item & 7;                                         \
            if (orient == 0) {                                                       \
                int h = (CKK)*8 + u;                                                 \
                if (h < NH) {                                                        \
                    const float4* src = (const float4*)(xb + (size_t)c*HW + h*NW + tile0); \
                    float4 v0 = src[0], v1 = src[1];                                 \
                    float* d = &tl[c*73 + u*9];                                      \
                    d[0]=v0.x; d[1]=v0.y; d[2]=v0.z; d[3]=v0.w;                      \
                    d[4]=v1.x; d[5]=v1.y; d[6]=v1.z; d[7]=v1.w;                      \
                }                                                                    \
            } else {                                                                 \
                int wc = (CKK)*8;                                                    \
                if (wc < NW) {                                                       \
                    const float4* src = (const float4*)(xb + (size_t)c*HW + (tile0+u)*NW + wc); \
                    float4 v0 = src[0], v1 = src[1];                                 \
                    float* d = &tl[c*73 + u];                                        \
                    d[0] =v0.x; d[9] =v0.y; d[18]=v0.z; d[27]=v0.w;                  \
                    d[36]=v1.x; d[45]=v1.y; d[54]=v1.z; d[63]=v1.w;                  \
                }                                                                    \
            }                                                                        \
        }                                                                            \
    }

    // full chunks: all 8 steps have sn <= o_hi+5
    int ckk = ck0;
    for (; ckk*8 + 7 <= o_hi + 5; ++ckk) {
        STAGE(ckk);
        #pragma unroll
        for (int j = 0; j < 8; ++j) STEP(j, ckk*8 + j);
    }
    // epilogue chunk: exactly 6 steps remain (sn = ckk*8 .. o_hi+5)
    {
        STAGE(ckk);
        #pragma unroll
        for (int j = 0; j < 6; ++j) STEP(j, ckk*8 + j);
    }
    #undef STEP
    #undef STAGE

    // accumulate partial Grams
    float* gl = &g_lrb[((orient*NB)+b)*4096];
    #pragma unroll
    for (int i = 0; i < 4; ++i)
        #pragma unroll
        for (int jj = 0; jj < 4; ++jj)
            atomicAdd(&gl[(trow*4+i)*64 + tcol*4 + jj], aL[i][jj]);
    float* gs = &g_srb[((orient*NB)+b)*512];
    atomicAdd(&gs[hq*64 + dd*8 + e0    ], aS0);
    atomicAdd(&gs[hq*64 + dd*8 + e0 + 1], aS1);

    // accumulate row/col sums (orient0 streams h -> column sums; orient1 -> row sums)
    if (orient == 0) {
        atomicAdd(&g_colsum[(b*64+cc)*NW + tile0 + p0    ], cs0);
        atomicAdd(&g_colsum[(b*64+cc)*NW + tile0 + p0 + 4], cs1);
    } else {
        atomicAdd(&g_rowsum[(b*64+cc)*NH + tile0 + p0    ], cs0);
        atomicAdd(&g_rowsum[(b*64+cc)*NH + tile0 + p0 + 4], cs1);
    }
}

// ---------------------------------------------------------------------------
// v_mean from row/col sums + v weights.
// total v-conv sum = wtot * S + edge corrections, S = sum of all 224 sums.
// grid (NB, 2), 256 threads: 4 threads per channel for the S reduction.
__global__ void vm_kernel(
    const float* __restrict__ lvh, const float* __restrict__ lvw,
    const float* __restrict__ svh, const float* __restrict__ svw)
{
    int b = blockIdx.x, which = blockIdx.y;
    int t = threadIdx.x;
    int c = t >> 2, l = t & 3;
    const float* sums = which ? &g_colsum[(b*64+c)*NW] : &g_rowsum[(b*64+c)*NH];

    float S = 0.f;
    for (int a2 = l; a2 < 224; a2 += 4) S += sums[a2];
    S += __shfl_xor_sync(0xffffffffu, S, 1);
    S += __shfl_xor_sync(0xffffffffu, S, 2);

    if (l == 0) {
        const float* wL = (which ? lvw : lvh) + c*21;
        const float* wS = (which ? svw : svh) + c*21;
        float wLr[21], wSr[21];
        #pragma unroll
        for (int i = 0; i < 21; ++i) { wLr[i] = wL[i]; wSr[i] = wS[i]; }
        float wLtot = 0.f, wStot = 0.f;
        #pragma unroll
        for (int i = 0; i < 21; ++i) { wLtot += wLr[i]; wStot += wSr[i]; }
        float accL = S * wLtot, accS = S * wStot;
        // left edge a=0..9: coeff = sum w[0..a+10]  -> add (coeff - wtot)*sums[a]
        {
            float cpL = 0.f, cpS = 0.f;
            #pragma unroll
            for (int i2 = 0; i2 <= 10; ++i2) { cpL += wLr[i2]; cpS += wSr[i2]; }
            #pragma unroll
            for (int a2 = 0; a2 < 10; ++a2) {
                float s = sums[a2];
                accL += s * (cpL - wLtot); accS += s * (cpS - wStot);
                cpL += wLr[11 + a2]; cpS += wSr[11 + a2];
            }
        }
        // right edge a=214..223: coeff = sum w[a-213..20]
        {
            float cpL = wLtot - wLr[0], cpS = wStot - wSr[0];
            #pragma unroll
            for (int a2 = 0; a2 < 10; ++a2) {
                float s = sums[214 + a2];
                accL += s * (cpL - wLtot); accS += s * (cpS - wStot);
                cpL -= wLr[1 + a2]; cpS -= wSr[1 + a2];
            }
        }
        g_vm[b][which*2 + 0][c] = accL * (1.f/50176.f);
        g_vm[b][which*2 + 1][c] = accS * (1.f/50176.f);
    }
}

// ---------------------------------------------------------------------------
// softmax(G), dot with v_mean, mix, sigmoid.
__global__ void attn_kernel(const float* __restrict__ mixw)
{
    int b = blockIdx.x, t = threadIdx.x;
    __shared__ float vm[4][64];
    __shared__ float res[4][64];
    {
        int slot = t >> 6, c = t & 63;
        vm[slot][c] = g_vm[b][slot][c];
    }
    __syncthreads();
    {
        int c = t & 63, role = t >> 6;     // 0 lrb-h, 1 lrb-w, 2 srb-h, 3 srb-w
        float r;
        if (role < 2) {
            const float* row = &g_lrb[((role*NB)+b)*4096 + c*64];
            const float* vmp = vm[role*2];
            float m = -1e30f;
            for (int e = 0; e < 64; ++e) { float v = row[e]*0.125f; if (v > m) m = v; }
            float se = 0.f, sd = 0.f;
            for (int e = 0; e < 64; ++e) {
                float ex = expf(row[e]*0.125f - m);
                se += ex; sd += ex*vmp[e];
            }
            r = sd/se;
        } else {
            int hh = c >> 3, ddd = c & 7;
            const float* row = &g_srb[(((role-2)*NB)+b)*512 + hh*64 + ddd*8];
            const float* vmp = vm[(role-2)*2 + 1] + hh*8;
            const float sc = 0.35355339059327373f;  // 8^-0.5
            float m = -1e30f;
            #pragma unroll
            for (int e = 0; e < 8; ++e) { float v = row[e]*sc; if (v > m) m = v; }
            float se = 0.f, sd = 0.f;
            #pragma unroll
            for (int e = 0; e < 8; ++e) {
                float ex = expf(row[e]*sc - m);
                se += ex; sd += ex*vmp[e];
            }
            r = sd/se;
        }
        res[role][c] = r;
    }
    __syncthreads();
    if (t < 64) {
        float a2 = mixw[0]*res[0][t] + mixw[1]*res[1][t]
                 + mixw[2]*res[2][t] + mixw[3]*res[3][t];
        g_gate[b*64 + t] = 1.f/(1.f + expf(-a2));
    }
}

// ---------------------------------------------------------------------------
__global__ void apply_kernel(const float* __restrict__ x, float* __restrict__ out) {
    int i = blockIdx.x*256 + threadIdx.x;      // over float4s
    if (i >= NB*NC*HW/4) return;
    float4 v = ((const float4*)x)[i];
    int bc = i / (HW/4);                       // HW/4 = 12544
    float s = g_gate[bc];
    v.x *= s; v.y *= s; v.z *= s; v.w *= s;
    ((float4*)out)[i] = v;
}

// ---------------------------------------------------------------------------
extern "C" void kernel_launch(void* const* d_in, const int* in_sizes, int n_in,
                              void* d_out, int out_size) {
    const float* x    = (const float*)d_in[0];
    const float* lqh  = (const float*)d_in[1];
    const float* lqw  = (const float*)d_in[2];
    const float* lkh  = (const float*)d_in[3];
    const float* lkw  = (const float*)d_in[4];
    const float* lvh  = (const float*)d_in[5];
    const float* lvw  = (const float*)d_in[6];
    const float* sqh  = (const float*)d_in[7];
    const float* sqw  = (const float*)d_in[8];
    const float* skh  = (const float*)d_in[9];
    const float* skw  = (const float*)d_in[10];
    const float* svh  = (const float*)d_in[11];
    const float* svw  = (const float*)d_in[12];
    const float* mixw = (const float*)d_in[13];
    float* out = (float*)d_out;

    zero_kernel<<<(NB*NC*NH + 255)/256, 256>>>();
    dim3 g(28, NB, 4);
    gram_kernel<<<g, 256>>>(x, lqh, lkh, sqh, skh, lqw, lkw, sqw, skw);
    vm_kernel<<<dim3(NB,2), 256>>>(lvh, lvw, svh, svw);
    attn_kernel<<<NB, 256>>>(mixw);
    apply_kernel<<<(NB*NC*HW/4 + 255)/256, 256>>>(x, out);
}